// round 1
// baseline (speedup 1.0000x reference)
#include <cuda_runtime.h>
#include <cmath>

// Problem constants
#define NTOK 8192      // B*T = 4*2048
#define DDIM 2048
#define NE   64
#define NCOL 128       // gate(64) ++ noise(64)
#define BK   16
#define BM   64

// Output layout (concatenated float32, reference return order):
//   router_probs [NTOK*NE]      @ 0
//   top_k_indices [NTOK*2]      @ 524288
//   exp_mask [2*NTOK*NE]        @ 540672
#define P_OFF 0
#define I_OFF (NTOK * NE)
#define M_OFF (I_OFF + NTOK * 2)

// Scratch for logits (gate | noise), packed as f32x2 pairs. 4 MiB.
__device__ __align__(16) unsigned long long g_logits2[NTOK * NCOL / 2];

__device__ __forceinline__ unsigned long long pack2(float x) {
    unsigned long long r;
    asm("mov.b64 %0, {%1, %1};" : "=l"(r) : "r"(__float_as_uint(x)));
    return r;
}
__device__ __forceinline__ void fma2(unsigned long long& d, unsigned long long a,
                                     unsigned long long b) {
    asm("fma.rn.f32x2 %0, %1, %2, %3;" : "=l"(d) : "l"(a), "l"(b), "l"(d));
}

// GEMM: logits[t][0:64]  = x[t,:] @ w_gate
//       logits[t][64:128]= x[t,:] @ w_noise
// Block: BM=64 tokens x 128 cols, 256 threads, each thread 4 tokens x 4 col-pairs.
__global__ __launch_bounds__(256, 1) void gemm_kernel(
    const float* __restrict__ x,
    const float* __restrict__ wg,
    const float* __restrict__ wn)
{
    __shared__ __align__(16) float As[BK][BM];    // [k][token]
    __shared__ __align__(16) float Bs[BK][NCOL];  // [k][col]

    const int tid = threadIdx.x;
    const int row0 = blockIdx.x * BM;
    const int rg = tid >> 4;       // 0..15 : token group (rows rg + 16*i)
    const int cg = tid & 15;       // 0..15 : pair group (pairs cg + 16*j)

    unsigned long long acc[4][4];
    const unsigned long long z2 = pack2(0.0f);
    #pragma unroll
    for (int i = 0; i < 4; i++)
        #pragma unroll
        for (int j = 0; j < 4; j++) acc[i][j] = z2;

    const int atok = tid >> 2;        // 0..63
    const int akq  = (tid & 3) * 4;   // 0,4,8,12
    const float4* xrow = reinterpret_cast<const float4*>(x + (long)(row0 + atok) * DDIM);

    for (int k0 = 0; k0 < DDIM; k0 += BK) {
        // --- load A tile (64x16), transposed into As[k][token] ---
        float4 av = xrow[(k0 + akq) >> 2];
        As[akq + 0][atok] = av.x;
        As[akq + 1][atok] = av.y;
        As[akq + 2][atok] = av.z;
        As[akq + 3][atok] = av.w;
        // --- load B tile (16x128): cols 0..63 = w_gate, 64..127 = w_noise ---
        #pragma unroll
        for (int l = 0; l < 2; l++) {
            int fid = tid + 256 * l;     // 0..511 float4 id
            int k   = fid >> 5;          // 0..15
            int c4  = fid & 31;          // 0..31
            float4 bv;
            int c;
            if (c4 < 16) {
                bv = reinterpret_cast<const float4*>(wg + (long)(k0 + k) * NE)[c4];
                c = c4 * 4;
            } else {
                bv = reinterpret_cast<const float4*>(wn + (long)(k0 + k) * NE)[c4 - 16];
                c = 64 + (c4 - 16) * 4;
            }
            *reinterpret_cast<float4*>(&Bs[k][c]) = bv;
        }
        __syncthreads();

        #pragma unroll
        for (int kk = 0; kk < BK; kk++) {
            const unsigned long long* Bp =
                reinterpret_cast<const unsigned long long*>(&Bs[kk][0]);
            unsigned long long a2[4], b2[4];
            #pragma unroll
            for (int i = 0; i < 4; i++) a2[i] = pack2(As[kk][rg + 16 * i]);
            #pragma unroll
            for (int j = 0; j < 4; j++) b2[j] = Bp[cg + 16 * j];
            #pragma unroll
            for (int i = 0; i < 4; i++)
                #pragma unroll
                for (int j = 0; j < 4; j++) fma2(acc[i][j], a2[i], b2[j]);
        }
        __syncthreads();
    }

    #pragma unroll
    for (int i = 0; i < 4; i++) {
        long r = row0 + rg + 16 * i;
        #pragma unroll
        for (int j = 0; j < 4; j++) {
            g_logits2[(r * NCOL) / 2 + cg + 16 * j] = acc[i][j];
        }
    }
}

__device__ __forceinline__ float softplus_f(float v) {
    // matches jax.nn.softplus = logaddexp(v, 0) within fp32 rounding
    return (v > 20.0f) ? v : log1pf(expf(v));
}

// One warp per token: noisy logits, top-2 (stable: smaller index wins ties),
// 2-way softmax, scatter all outputs.
__global__ __launch_bounds__(256) void router_kernel(
    const float* __restrict__ eps, float* __restrict__ out)
{
    const int warp = threadIdx.x >> 5;
    const int lane = threadIdx.x & 31;
    const int t = blockIdx.x * 8 + warp;
    const float* gl = reinterpret_cast<const float*>(g_logits2) + (long)t * NCOL;

    // lane handles experts e0 = lane, e1 = lane + 32
    float g0 = gl[lane];
    float g1 = gl[lane + 32];
    float n0 = gl[64 + lane];
    float n1 = gl[96 + lane];
    float ep0 = eps[(long)t * NE + lane];
    float ep1 = eps[(long)t * NE + lane + 32];
    float l0 = g0 + softplus_f(n0) * ep0;
    float l1 = g1 + softplus_f(n1) * ep1;

    // top-1 (value max, ties -> smaller index)
    float bv; int bi;
    if (l0 >= l1) { bv = l0; bi = lane; } else { bv = l1; bi = lane + 32; }
    #pragma unroll
    for (int off = 16; off; off >>= 1) {
        float ov = __shfl_xor_sync(0xffffffffu, bv, off);
        int   oi = __shfl_xor_sync(0xffffffffu, bi, off);
        if (ov > bv || (ov == bv && oi < bi)) { bv = ov; bi = oi; }
    }
    const float v1 = bv; const int i1 = bi;

    // top-2: exclude i1
    float c0 = (lane == i1)        ? -INFINITY : l0;
    float c1 = ((lane + 32) == i1) ? -INFINITY : l1;
    if (c0 >= c1) { bv = c0; bi = lane; } else { bv = c1; bi = lane + 32; }
    #pragma unroll
    for (int off = 16; off; off >>= 1) {
        float ov = __shfl_xor_sync(0xffffffffu, bv, off);
        int   oi = __shfl_xor_sync(0xffffffffu, bi, off);
        if (ov > bv || (ov == bv && oi < bi)) { bv = ov; bi = oi; }
    }
    const float v2 = bv; const int i2 = bi;

    // softmax over {v1, v2}, v1 >= v2
    float e  = expf(v2 - v1);
    float p1 = 1.0f / (1.0f + e);
    float p2 = e * p1;

    // router_probs
    float pr0 = (lane == i1) ? p1 : ((lane == i2) ? p2 : 0.0f);
    float pr1 = ((lane + 32) == i1) ? p1 : (((lane + 32) == i2) ? p2 : 0.0f);
    out[P_OFF + (long)t * NE + lane]      = pr0;
    out[P_OFF + (long)t * NE + lane + 32] = pr1;

    // top_k_indices (as float)
    if (lane == 0) {
        out[I_OFF + (long)t * 2 + 0] = (float)i1;
        out[I_OFF + (long)t * 2 + 1] = (float)i2;
    }

    // exp_mask [2][NTOK][NE]
    out[M_OFF + (long)t * NE + lane]      = (lane == i1) ? 1.0f : 0.0f;
    out[M_OFF + (long)t * NE + lane + 32] = ((lane + 32) == i1) ? 1.0f : 0.0f;
    out[M_OFF + (long)NTOK * NE + (long)t * NE + lane]      = (lane == i2) ? 1.0f : 0.0f;
    out[M_OFF + (long)NTOK * NE + (long)t * NE + lane + 32] = ((lane + 32) == i2) ? 1.0f : 0.0f;
}

extern "C" void kernel_launch(void* const* d_in, const int* in_sizes, int n_in,
                              void* d_out, int out_size)
{
    const float* x   = (const float*)d_in[0];  // [4,2048,2048]
    const float* eps = (const float*)d_in[1];  // [4,2048,64]
    const float* wg  = (const float*)d_in[2];  // [2048,64]
    const float* wn  = (const float*)d_in[3];  // [2048,64]
    float* out = (float*)d_out;

    gemm_kernel<<<NTOK / BM, 256>>>(x, wg, wn);
    router_kernel<<<NTOK / 8, 256>>>(eps, out);
}

// round 3
// speedup vs baseline: 1.9495x; 1.9495x over previous
#include <cuda_runtime.h>
#include <cuda_bf16.h>
#include <cstdint>
#include <cmath>

// ---------------- problem constants ----------------
#define NTOK 8192      // B*T
#define DDIM 2048
#define NE   64

// output layout (concatenated float32)
#define P_OFF 0
#define I_OFF (NTOK * NE)
#define M_OFF (I_OFF + NTOK * 2)

// ---------------- GEMM tiling ----------------
#define KSPLIT 4
#define KQ     512            // K per split
#define CHK    16             // k per chunk (one k16 mma step)
#define NCH    32             // chunks per CTA (KQ/CHK)
#define AROW   48             // smem row stride bytes (32B data + 16B pad)
#define A_PL   (256 * AROW)   // one A plane: 256 tokens
#define B_PL   (128 * AROW)   // one B plane: 128 cols
#define A_SZ   (3 * A_PL)
#define B_SZ   (3 * B_PL)
#define BUF    (A_SZ + B_SZ)  // 55296
#define SMEMB  (2 * BUF)      // 110592, double buffered

// ---------------- scratch ----------------
__device__ __align__(16) __nv_bfloat16 g_B[3 * 128 * 2048];   // [plane][col][k]
__device__ float g_part[KSPLIT * NTOK * 128];                  // k-split partials

// ---------------- helpers ----------------
__device__ __forceinline__ uint32_t smem_u32(const void* p) {
    uint32_t a;
    asm("{ .reg .u64 t; cvta.to.shared.u64 t, %1; cvt.u32.u64 %0, t; }" : "=r"(a) : "l"(p));
    return a;
}
#define CP16(dst, src) \
    asm volatile("cp.async.cg.shared.global [%0], [%1], 16;" :: "r"(dst), "l"(src) : "memory")
#define CP_COMMIT() asm volatile("cp.async.commit_group;" ::: "memory")
#define CP_WAIT0()  asm volatile("cp.async.wait_group 0;" ::: "memory")

__device__ __forceinline__ void ldsm4(uint32_t (&r)[4], uint32_t addr) {
    asm volatile("ldmatrix.sync.aligned.m8n8.x4.shared.b16 {%0,%1,%2,%3}, [%4];"
                 : "=r"(r[0]), "=r"(r[1]), "=r"(r[2]), "=r"(r[3]) : "r"(addr));
}
__device__ __forceinline__ void mma16816(float (&c)[4], const uint32_t (&a)[4],
                                         uint32_t b0, uint32_t b1) {
    asm volatile(
        "mma.sync.aligned.m16n8k16.row.col.f32.bf16.bf16.f32 "
        "{%0,%1,%2,%3},{%4,%5,%6,%7},{%8,%9},{%0,%1,%2,%3};"
        : "+f"(c[0]), "+f"(c[1]), "+f"(c[2]), "+f"(c[3])
        : "r"(a[0]), "r"(a[1]), "r"(a[2]), "r"(a[3]), "r"(b0), "r"(b1));
}
__device__ __forceinline__ uint32_t bf2_bits(__nv_bfloat162 v) {
    return *reinterpret_cast<uint32_t*>(&v);
}

// split 8 fp32 -> 3 planes of 8 bf16 (packed uint4 each)
__device__ __forceinline__ void split8(const float* f, uint4& H, uint4& M, uint4& L) {
    uint32_t hw[4], mw[4], lw[4];
    #pragma unroll
    for (int i = 0; i < 4; i++) {
        float a = f[2 * i], b = f[2 * i + 1];
        __nv_bfloat162 hp = __floats2bfloat162_rn(a, b);
        float ra = a - __bfloat162float(__low2bfloat16(hp));
        float rb = b - __bfloat162float(__high2bfloat16(hp));
        __nv_bfloat162 mp = __floats2bfloat162_rn(ra, rb);
        float sa = ra - __bfloat162float(__low2bfloat16(mp));
        float sb = rb - __bfloat162float(__high2bfloat16(mp));
        __nv_bfloat162 lp = __floats2bfloat162_rn(sa, sb);
        hw[i] = bf2_bits(hp); mw[i] = bf2_bits(mp); lw[i] = bf2_bits(lp);
    }
    H = make_uint4(hw[0], hw[1], hw[2], hw[3]);
    M = make_uint4(mw[0], mw[1], mw[2], mw[3]);
    L = make_uint4(lw[0], lw[1], lw[2], lw[3]);
}

// ---------------- prep: w -> g_B[3][128 col][2048 k] bf16 planes ----------------
__global__ __launch_bounds__(256) void prep_b(const float* __restrict__ wg,
                                              const float* __restrict__ wn) {
    int n  = threadIdx.x & 63;
    int kq = threadIdx.x >> 6;                 // 0..3
    int k0 = blockIdx.x * 32 + kq * 8;
    #pragma unroll
    for (int h = 0; h < 2; h++) {
        const float* w = h ? wn : wg;
        float f[8];
        #pragma unroll
        for (int i = 0; i < 8; i++) f[i] = w[(k0 + i) * 64 + n];
        uint4 H, M, L;
        split8(f, H, M, L);
        int row = h * 64 + n;
        *reinterpret_cast<uint4*>(&g_B[(0 * 128 + row) * 2048 + k0]) = H;
        *reinterpret_cast<uint4*>(&g_B[(1 * 128 + row) * 2048 + k0]) = M;
        *reinterpret_cast<uint4*>(&g_B[(2 * 128 + row) * 2048 + k0]) = L;
    }
}

// ---------------- main GEMM: mma.sync bf16, 6-term split, split-K x4 ----------------
__global__ __launch_bounds__(512, 1) void gemm_mma_kernel(const float* __restrict__ x) {
    extern __shared__ char smem[];
    const uint32_t sb = smem_u32(smem);
    const int tid  = threadIdx.x;
    const int wid  = tid >> 5;
    const int lane = tid & 31;
    const int tile = blockIdx.x >> 2;
    const int ks   = blockIdx.x & 3;
    const long t0  = (long)tile * 256;
    const int kbase = ks * KQ;

    const int m0 = (wid & 3) * 64;     // warp m-group
    const int n0 = (wid >> 2) * 32;    // warp n-group

    const int am  = tid >> 1;          // A fill: token row
    const int akb = (tid & 1) * 16;    // A fill: 16B half (8 k)

    float acc[4][4][4];
    #pragma unroll
    for (int a = 0; a < 4; a++)
        #pragma unroll
        for (int b = 0; b < 4; b++)
            #pragma unroll
            for (int c = 0; c < 4; c++) acc[a][b][c] = 0.0f;

    const int t4 = lane >> 3, r8 = lane & 7;
    const uint32_t a_lane = (uint32_t)(((t4 & 1) * 8 + r8) * AROW + (t4 >> 1) * 16);
    const uint32_t b_lane = (uint32_t)(((t4 >> 1) * 8 + r8) * AROW + (t4 & 1) * 16);

    // ---- prologue: chunk 0 ----
    {
        const float4* p = reinterpret_cast<const float4*>(
            x + (t0 + am) * DDIM + kbase + (tid & 1) * 8);
        float4 xa = p[0], xb = p[1];
        float f[8] = {xa.x, xa.y, xa.z, xa.w, xb.x, xb.y, xb.z, xb.w};
        uint4 H, M, L;
        split8(f, H, M, L);
        *reinterpret_cast<uint4*>(smem + 0 * A_PL + am * AROW + akb) = H;
        *reinterpret_cast<uint4*>(smem + 1 * A_PL + am * AROW + akb) = M;
        *reinterpret_cast<uint4*>(smem + 2 * A_PL + am * AROW + akb) = L;
        // B chunk 0 via cp.async
        {
            int seg = tid, plane = seg >> 8, rem = seg & 255, row = rem >> 1, kg = rem & 1;
            const __nv_bfloat16* src = g_B + (plane * 128 + row) * 2048 + kbase + kg * 8;
            CP16(sb + A_SZ + plane * B_PL + row * AROW + kg * 16, src);
        }
        if (tid < 256) {
            int seg = 512 + tid, plane = seg >> 8, rem = seg & 255, row = rem >> 1, kg = rem & 1;
            const __nv_bfloat16* src = g_B + (plane * 128 + row) * 2048 + kbase + kg * 8;
            CP16(sb + A_SZ + plane * B_PL + row * AROW + kg * 16, src);
        }
        CP_COMMIT();
    }

    #pragma unroll 1
    for (int c = 0; c < NCH; c++) {
        const uint32_t cur = (uint32_t)((c & 1) * BUF);
        const uint32_t nxt = (uint32_t)(((c + 1) & 1) * BUF);

        // stage next chunk's x in registers
        float4 xa, xb;
        if (c + 1 < NCH) {
            const float4* p = reinterpret_cast<const float4*>(
                x + (t0 + am) * DDIM + kbase + (c + 1) * CHK + (tid & 1) * 8);
            xa = p[0]; xb = p[1];
        }

        CP_WAIT0();
        __syncthreads();   // buffer c ready; all reads of buffer (c-1) done

        if (c + 1 < NCH) {
            float f[8] = {xa.x, xa.y, xa.z, xa.w, xb.x, xb.y, xb.z, xb.w};
            uint4 H, M, L;
            split8(f, H, M, L);
            *reinterpret_cast<uint4*>(smem + nxt + 0 * A_PL + am * AROW + akb) = H;
            *reinterpret_cast<uint4*>(smem + nxt + 1 * A_PL + am * AROW + akb) = M;
            *reinterpret_cast<uint4*>(smem + nxt + 2 * A_PL + am * AROW + akb) = L;
            int kg0 = kbase + (c + 1) * CHK;
            {
                int seg = tid, plane = seg >> 8, rem = seg & 255, row = rem >> 1, kg = rem & 1;
                const __nv_bfloat16* src = g_B + (plane * 128 + row) * 2048 + kg0 + kg * 8;
                CP16(sb + nxt + A_SZ + plane * B_PL + row * AROW + kg * 16, src);
            }
            if (tid < 256) {
                int seg = 512 + tid, plane = seg >> 8, rem = seg & 255, row = rem >> 1, kg = seg & 1;
                const __nv_bfloat16* src = g_B + (plane * 128 + row) * 2048 + kg0 + kg * 8;
                CP16(sb + nxt + A_SZ + plane * B_PL + row * AROW + kg * 16, src);
            }
            CP_COMMIT();
        }
        __syncthreads();   // buffer c's A stores visible

        // ---- compute on buffer c: 6 plane-pairs, A-frag reuse over pb ----
        const uint32_t aB = sb + cur;
        const uint32_t bB = sb + cur + A_SZ;
        #pragma unroll
        for (int pa = 0; pa < 3; pa++) {
            uint32_t Af[4][4];
            #pragma unroll
            for (int mf = 0; mf < 4; mf++)
                ldsm4(Af[mf], aB + pa * A_PL + (uint32_t)((m0 + mf * 16) * AROW) + a_lane);
            const int npb = 3 - pa;   // pa=0:{0,1,2} pa=1:{0,1} pa=2:{0}
            #pragma unroll
            for (int pb = 0; pb < 3; pb++) {
                if (pb >= npb) break;
                uint32_t Bf[2][4];
                #pragma unroll
                for (int q = 0; q < 2; q++)
                    ldsm4(Bf[q], bB + pb * B_PL + (uint32_t)((n0 + q * 16) * AROW) + b_lane);
                #pragma unroll
                for (int mf = 0; mf < 4; mf++)
                    #pragma unroll
                    for (int nf = 0; nf < 4; nf++)
                        mma16816(acc[mf][nf], Af[mf],
                                 Bf[nf >> 1][(nf & 1) * 2], Bf[nf >> 1][(nf & 1) * 2 + 1]);
            }
        }
    }

    // ---- epilogue: write k-split partial sums ----
    float* gp = g_part + (long)ks * NTOK * 128;
    #pragma unroll
    for (int mf = 0; mf < 4; mf++) {
        int tok = (int)t0 + m0 + mf * 16 + (lane >> 2);
        #pragma unroll
        for (int nf = 0; nf < 4; nf++) {
            int col = n0 + nf * 8 + (lane & 3) * 2;
            *reinterpret_cast<float2*>(&gp[(long)tok * 128 + col]) =
                make_float2(acc[mf][nf][0], acc[mf][nf][1]);
            *reinterpret_cast<float2*>(&gp[(long)(tok + 8) * 128 + col]) =
                make_float2(acc[mf][nf][2], acc[mf][nf][3]);
        }
    }
}

// ---------------- router epilogue ----------------
__device__ __forceinline__ float softplus_f(float v) {
    return (v > 20.0f) ? v : log1pf(expf(v));
}

__global__ __launch_bounds__(256) void router_kernel(
    const float* __restrict__ eps, float* __restrict__ out)
{
    const int warp = threadIdx.x >> 5;
    const int lane = threadIdx.x & 31;
    const int t = blockIdx.x * 8 + warp;

    float g0 = 0, g1 = 0, n0 = 0, n1 = 0;
    #pragma unroll
    for (int s = 0; s < KSPLIT; s++) {
        const float* P = g_part + ((long)s * NTOK + t) * 128;
        g0 += P[lane];       g1 += P[lane + 32];
        n0 += P[64 + lane];  n1 += P[96 + lane];
    }
    float ep0 = eps[(long)t * NE + lane];
    float ep1 = eps[(long)t * NE + lane + 32];
    float l0 = g0 + softplus_f(n0) * ep0;
    float l1 = g1 + softplus_f(n1) * ep1;

    float bv; int bi;
    if (l0 >= l1) { bv = l0; bi = lane; } else { bv = l1; bi = lane + 32; }
    #pragma unroll
    for (int off = 16; off; off >>= 1) {
        float ov = __shfl_xor_sync(0xffffffffu, bv, off);
        int   oi = __shfl_xor_sync(0xffffffffu, bi, off);
        if (ov > bv || (ov == bv && oi < bi)) { bv = ov; bi = oi; }
    }
    const float v1 = bv; const int i1 = bi;

    float c0 = (lane == i1)        ? -INFINITY : l0;
    float c1 = ((lane + 32) == i1) ? -INFINITY : l1;
    if (c0 >= c1) { bv = c0; bi = lane; } else { bv = c1; bi = lane + 32; }
    #pragma unroll
    for (int off = 16; off; off >>= 1) {
        float ov = __shfl_xor_sync(0xffffffffu, bv, off);
        int   oi = __shfl_xor_sync(0xffffffffu, bi, off);
        if (ov > bv || (ov == bv && oi < bi)) { bv = ov; bi = oi; }
    }
    const float v2 = bv; const int i2 = bi;

    float e  = expf(v2 - v1);
    float p1 = 1.0f / (1.0f + e);
    float p2 = e * p1;

    float pr0 = (lane == i1) ? p1 : ((lane == i2) ? p2 : 0.0f);
    float pr1 = ((lane + 32) == i1) ? p1 : (((lane + 32) == i2) ? p2 : 0.0f);
    out[P_OFF + (long)t * NE + lane]      = pr0;
    out[P_OFF + (long)t * NE + lane + 32] = pr1;

    if (lane == 0) {
        out[I_OFF + (long)t * 2 + 0] = (float)i1;
        out[I_OFF + (long)t * 2 + 1] = (float)i2;
    }

    out[M_OFF + (long)t * NE + lane]      = (lane == i1) ? 1.0f : 0.0f;
    out[M_OFF + (long)t * NE + lane + 32] = ((lane + 32) == i1) ? 1.0f : 0.0f;
    out[M_OFF + (long)NTOK * NE + (long)t * NE + lane]      = (lane == i2) ? 1.0f : 0.0f;
    out[M_OFF + (long)NTOK * NE + (long)t * NE + lane + 32] = ((lane + 32) == i2) ? 1.0f : 0.0f;
}

extern "C" void kernel_launch(void* const* d_in, const int* in_sizes, int n_in,
                              void* d_out, int out_size)
{
    const float* x   = (const float*)d_in[0];  // [4,2048,2048]
    const float* eps = (const float*)d_in[1];  // [4,2048,64]
    const float* wg  = (const float*)d_in[2];  // [2048,64]
    const float* wn  = (const float*)d_in[3];  // [2048,64]
    float* out = (float*)d_out;

    cudaFuncSetAttribute(gemm_mma_kernel, cudaFuncAttributeMaxDynamicSharedMemorySize, SMEMB);
    prep_b<<<64, 256>>>(wg, wn);
    gemm_mma_kernel<<<128, 512, SMEMB>>>(x);
    router_kernel<<<NTOK / 8, 256>>>(eps, out);
}

// round 4
// speedup vs baseline: 2.5118x; 1.2885x over previous
#include <cuda_runtime.h>
#include <cuda_fp16.h>
#include <cstdint>
#include <cmath>

// ---------------- problem constants ----------------
#define NTOK 8192      // B*T
#define DDIM 2048
#define NE   64

// output layout (concatenated float32)
#define P_OFF 0
#define I_OFF (NTOK * NE)
#define M_OFF (I_OFF + NTOK * 2)

// ---------------- GEMM tiling ----------------
#define KSPLIT 2
#define KQ     1024           // K per split
#define CHK    32             // k per chunk (2 k16 mma steps)
#define NCH    32             // chunks (KQ/CHK)
#define AROW   80             // smem row stride bytes (64B data + 16B pad)
#define A_PL   (128 * AROW)   // one A plane: 128 tokens
#define B_PL   (128 * AROW)   // one B plane: 128 cols
#define A_SZ   (2 * A_PL)
#define B_SZ   (2 * B_PL)
#define BUF    (A_SZ + B_SZ)  // 40960
#define SMEMB  (2 * BUF)      // 81920, double buffered

// ---------------- scratch ----------------
__device__ __align__(16) __half g_B[2 * 128 * 2048];   // [plane][col][k]
__device__ float g_part[KSPLIT * NTOK * 128];          // k-split partials (8MB)

// ---------------- helpers ----------------
__device__ __forceinline__ uint32_t smem_u32(const void* p) {
    uint32_t a;
    asm("{ .reg .u64 t; cvta.to.shared.u64 t, %1; cvt.u32.u64 %0, t; }" : "=r"(a) : "l"(p));
    return a;
}
#define CP16(dst, src) \
    asm volatile("cp.async.cg.shared.global [%0], [%1], 16;" :: "r"(dst), "l"(src) : "memory")
#define CP_COMMIT() asm volatile("cp.async.commit_group;" ::: "memory")
#define CP_WAIT0()  asm volatile("cp.async.wait_group 0;" ::: "memory")

__device__ __forceinline__ void ldsm4(uint32_t (&r)[4], uint32_t addr) {
    asm volatile("ldmatrix.sync.aligned.m8n8.x4.shared.b16 {%0,%1,%2,%3}, [%4];"
                 : "=r"(r[0]), "=r"(r[1]), "=r"(r[2]), "=r"(r[3]) : "r"(addr));
}
__device__ __forceinline__ void mma16816(float (&c)[4], const uint32_t (&a)[4],
                                         uint32_t b0, uint32_t b1) {
    asm volatile(
        "mma.sync.aligned.m16n8k16.row.col.f32.f16.f16.f32 "
        "{%0,%1,%2,%3},{%4,%5,%6,%7},{%8,%9},{%0,%1,%2,%3};"
        : "+f"(c[0]), "+f"(c[1]), "+f"(c[2]), "+f"(c[3])
        : "r"(a[0]), "r"(a[1]), "r"(a[2]), "r"(a[3]), "r"(b0), "r"(b1));
}
__device__ __forceinline__ uint32_t h2_bits(__half2 v) {
    return *reinterpret_cast<uint32_t*>(&v);
}

// split 8 fp32 -> 2 planes of 8 fp16 (packed uint4 each)
__device__ __forceinline__ void split8h(const float* f, uint4& H, uint4& L) {
    uint32_t hw[4], lw[4];
    #pragma unroll
    for (int i = 0; i < 4; i++) {
        float a = f[2 * i], b = f[2 * i + 1];
        __half2 hp = __floats2half2_rn(a, b);
        float ra = a - __low2float(hp);
        float rb = b - __high2float(hp);
        __half2 lp = __floats2half2_rn(ra, rb);
        hw[i] = h2_bits(hp); lw[i] = h2_bits(lp);
    }
    H = make_uint4(hw[0], hw[1], hw[2], hw[3]);
    L = make_uint4(lw[0], lw[1], lw[2], lw[3]);
}

// ---------------- prep: w -> g_B[2][128 col][2048 k] fp16, via smem transpose ----------------
__global__ __launch_bounds__(256) void prep_b(const float* __restrict__ wg,
                                              const float* __restrict__ wn) {
    __shared__ __align__(16) __half sh[2][128][36];  // [plane][row][32k + pad]
    const int tid = threadIdx.x;
    const int k0 = blockIdx.x * 32;

    // phase 1: coalesced reads, split, smem store (transposed layout)
    #pragma unroll
    for (int i = 0; i < 16; i++) {
        int fid = i * 256 + tid;            // 0..4095
        int h  = fid >> 11;                 // 0=gate 1=noise
        int kk = (fid >> 6) & 31;
        int n  = fid & 63;
        float a = (h ? wn : wg)[(k0 + kk) * 64 + n];
        __half hh = __float2half_rn(a);
        __half hl = __float2half_rn(a - __half2float(hh));
        sh[0][h * 64 + n][kk] = hh;
        sh[1][h * 64 + n][kk] = hl;
    }
    __syncthreads();

    // phase 2: coalesced 8B writes to gmem
    #pragma unroll
    for (int i = 0; i < 8; i++) {
        int fid = i * 256 + tid;            // 0..2047
        int plane = fid >> 10;
        int rem = fid & 1023;
        int row = rem >> 3;
        int kq  = rem & 7;                  // 4 halves each
        uint2 v = *reinterpret_cast<const uint2*>(&sh[plane][row][kq * 4]);
        *reinterpret_cast<uint2*>(&g_B[(plane * 128 + row) * 2048 + k0 + kq * 4]) = v;
    }
}

// ---------------- main GEMM: mma.sync fp16 2-plane (hh+hl+lh), split-K x2 ----------------
__global__ __launch_bounds__(512, 1) void gemm_mma_kernel(const float* __restrict__ x) {
    extern __shared__ char smem[];
    const uint32_t sb = smem_u32(smem);
    const int tid  = threadIdx.x;
    const int wid  = tid >> 5;
    const int lane = tid & 31;
    const int tile = blockIdx.x >> 1;
    const int ks   = blockIdx.x & 1;
    const long t0  = (long)tile * 128;
    const int kbase = ks * KQ;

    const int m0 = (wid & 3) * 32;     // warp m-group (32 tokens)
    const int n0 = (wid >> 2) * 32;    // warp n-group (32 cols)

    const int am = tid >> 2;           // A fill: token row (0..127)
    const int aq = tid & 3;            // A fill: 16B slot (8 k)

    float acc[2][4][4];
    #pragma unroll
    for (int a = 0; a < 2; a++)
        #pragma unroll
        for (int b = 0; b < 4; b++)
            #pragma unroll
            for (int c = 0; c < 4; c++) acc[a][b][c] = 0.0f;

    const int t4 = lane >> 3, r8 = lane & 7;
    const uint32_t a_lane = (uint32_t)(((t4 & 1) * 8 + r8) * AROW + (t4 >> 1) * 16);
    const uint32_t b_lane = (uint32_t)(((t4 >> 1) * 8 + r8) * AROW + (t4 & 1) * 16);

    // ---- prologue: chunk 0 ----
    {
        const float4* p = reinterpret_cast<const float4*>(
            x + (t0 + am) * DDIM + kbase + aq * 8);
        float4 xa = p[0], xb = p[1];
        float f[8] = {xa.x, xa.y, xa.z, xa.w, xb.x, xb.y, xb.z, xb.w};
        uint4 H, L;
        split8h(f, H, L);
        *reinterpret_cast<uint4*>(smem + 0 * A_PL + am * AROW + aq * 16) = H;
        *reinterpret_cast<uint4*>(smem + 1 * A_PL + am * AROW + aq * 16) = L;
        #pragma unroll
        for (int i = 0; i < 2; i++) {
            int seg = tid + 512 * i;
            int plane = seg >> 9, rem = seg & 511, row = rem >> 2, kq = rem & 3;
            const __half* src = g_B + (plane * 128 + row) * 2048 + kbase + kq * 8;
            CP16(sb + A_SZ + plane * B_PL + row * AROW + kq * 16, src);
        }
        CP_COMMIT();
    }

    #pragma unroll 1
    for (int c = 0; c < NCH; c++) {
        const uint32_t cur = (uint32_t)((c & 1) * BUF);
        const uint32_t nxt = (uint32_t)(((c + 1) & 1) * BUF);

        // stage next chunk's x in registers
        float4 xa, xb;
        if (c + 1 < NCH) {
            const float4* p = reinterpret_cast<const float4*>(
                x + (t0 + am) * DDIM + kbase + (c + 1) * CHK + aq * 8);
            xa = p[0]; xb = p[1];
        }

        CP_WAIT0();
        __syncthreads();   // buffer c ready; reads of buffer c-1 complete

        if (c + 1 < NCH) {
            float f[8] = {xa.x, xa.y, xa.z, xa.w, xb.x, xb.y, xb.z, xb.w};
            uint4 H, L;
            split8h(f, H, L);
            *reinterpret_cast<uint4*>(smem + nxt + 0 * A_PL + am * AROW + aq * 16) = H;
            *reinterpret_cast<uint4*>(smem + nxt + 1 * A_PL + am * AROW + aq * 16) = L;
            int kg0 = kbase + (c + 1) * CHK;
            #pragma unroll
            for (int i = 0; i < 2; i++) {
                int seg = tid + 512 * i;
                int plane = seg >> 9, rem = seg & 511, row = rem >> 2, kq = rem & 3;
                const __half* src = g_B + (plane * 128 + row) * 2048 + kg0 + kq * 8;
                CP16(sb + nxt + A_SZ + plane * B_PL + row * AROW + kq * 16, src);
            }
            CP_COMMIT();
        }
        __syncthreads();   // A stores for buffer c+1 ordered; buffer c safe to read

        // ---- compute on buffer c: terms hh, hl, lh over 2 k-steps ----
        const uint32_t aB = sb + cur;
        const uint32_t bB = sb + cur + A_SZ;
        #pragma unroll
        for (int s = 0; s < 2; s++) {
            uint32_t Ah[2][4], Al[2][4], Bh[2][4], Bl[2][4];
            #pragma unroll
            for (int mf = 0; mf < 2; mf++) {
                uint32_t base = aB + (uint32_t)((m0 + mf * 16) * AROW) + a_lane + s * 32;
                ldsm4(Ah[mf], base);
                ldsm4(Al[mf], base + A_PL);
            }
            #pragma unroll
            for (int q = 0; q < 2; q++) {
                uint32_t base = bB + (uint32_t)((n0 + q * 16) * AROW) + b_lane + s * 32;
                ldsm4(Bh[q], base);
                ldsm4(Bl[q], base + B_PL);
            }
            #pragma unroll
            for (int mf = 0; mf < 2; mf++)
                #pragma unroll
                for (int nf = 0; nf < 4; nf++) {
                    uint32_t bh0 = Bh[nf >> 1][(nf & 1) * 2], bh1 = Bh[nf >> 1][(nf & 1) * 2 + 1];
                    uint32_t bl0 = Bl[nf >> 1][(nf & 1) * 2], bl1 = Bl[nf >> 1][(nf & 1) * 2 + 1];
                    mma16816(acc[mf][nf], Ah[mf], bh0, bh1);
                    mma16816(acc[mf][nf], Ah[mf], bl0, bl1);
                    mma16816(acc[mf][nf], Al[mf], bh0, bh1);
                }
        }
    }

    // ---- epilogue: write k-split partial sums ----
    float* gp = g_part + (long)ks * NTOK * 128;
    #pragma unroll
    for (int mf = 0; mf < 2; mf++) {
        int tok = (int)t0 + m0 + mf * 16 + (lane >> 2);
        #pragma unroll
        for (int nf = 0; nf < 4; nf++) {
            int col = n0 + nf * 8 + (lane & 3) * 2;
            *reinterpret_cast<float2*>(&gp[(long)tok * 128 + col]) =
                make_float2(acc[mf][nf][0], acc[mf][nf][1]);
            *reinterpret_cast<float2*>(&gp[(long)(tok + 8) * 128 + col]) =
                make_float2(acc[mf][nf][2], acc[mf][nf][3]);
        }
    }
}

// ---------------- router epilogue ----------------
__device__ __forceinline__ float softplus_f(float v) {
    return (v > 20.0f) ? v : log1pf(expf(v));
}

__global__ __launch_bounds__(256) void router_kernel(
    const float* __restrict__ eps, float* __restrict__ out)
{
    const int warp = threadIdx.x >> 5;
    const int lane = threadIdx.x & 31;
    const int t = blockIdx.x * 8 + warp;

    float g0 = 0, g1 = 0, n0 = 0, n1 = 0;
    #pragma unroll
    for (int s = 0; s < KSPLIT; s++) {
        const float* P = g_part + ((long)s * NTOK + t) * 128;
        g0 += P[lane];       g1 += P[lane + 32];
        n0 += P[64 + lane];  n1 += P[96 + lane];
    }
    float ep0 = eps[(long)t * NE + lane];
    float ep1 = eps[(long)t * NE + lane + 32];
    float l0 = g0 + softplus_f(n0) * ep0;
    float l1 = g1 + softplus_f(n1) * ep1;

    float bv; int bi;
    if (l0 >= l1) { bv = l0; bi = lane; } else { bv = l1; bi = lane + 32; }
    #pragma unroll
    for (int off = 16; off; off >>= 1) {
        float ov = __shfl_xor_sync(0xffffffffu, bv, off);
        int   oi = __shfl_xor_sync(0xffffffffu, bi, off);
        if (ov > bv || (ov == bv && oi < bi)) { bv = ov; bi = oi; }
    }
    const float v1 = bv; const int i1 = bi;

    float c0 = (lane == i1)        ? -INFINITY : l0;
    float c1 = ((lane + 32) == i1) ? -INFINITY : l1;
    if (c0 >= c1) { bv = c0; bi = lane; } else { bv = c1; bi = lane + 32; }
    #pragma unroll
    for (int off = 16; off; off >>= 1) {
        float ov = __shfl_xor_sync(0xffffffffu, bv, off);
        int   oi = __shfl_xor_sync(0xffffffffu, bi, off);
        if (ov > bv || (ov == bv && oi < bi)) { bv = ov; bi = oi; }
    }
    const float v2 = bv; const int i2 = bi;

    float e  = expf(v2 - v1);
    float p1 = 1.0f / (1.0f + e);
    float p2 = e * p1;

    float pr0 = (lane == i1) ? p1 : ((lane == i2) ? p2 : 0.0f);
    float pr1 = ((lane + 32) == i1) ? p1 : (((lane + 32) == i2) ? p2 : 0.0f);
    out[P_OFF + (long)t * NE + lane]      = pr0;
    out[P_OFF + (long)t * NE + lane + 32] = pr1;

    if (lane == 0) {
        out[I_OFF + (long)t * 2 + 0] = (float)i1;
        out[I_OFF + (long)t * 2 + 1] = (float)i2;
    }

    out[M_OFF + (long)t * NE + lane]      = (lane == i1) ? 1.0f : 0.0f;
    out[M_OFF + (long)t * NE + lane + 32] = ((lane + 32) == i1) ? 1.0f : 0.0f;
    out[M_OFF + (long)NTOK * NE + (long)t * NE + lane]      = (lane == i2) ? 1.0f : 0.0f;
    out[M_OFF + (long)NTOK * NE + (long)t * NE + lane + 32] = ((lane + 32) == i2) ? 1.0f : 0.0f;
}

extern "C" void kernel_launch(void* const* d_in, const int* in_sizes, int n_in,
                              void* d_out, int out_size)
{
    const float* x   = (const float*)d_in[0];  // [4,2048,2048]
    const float* eps = (const float*)d_in[1];  // [4,2048,64]
    const float* wg  = (const float*)d_in[2];  // [2048,64]
    const float* wn  = (const float*)d_in[3];  // [2048,64]
    float* out = (float*)d_out;

    cudaFuncSetAttribute(gemm_mma_kernel, cudaFuncAttributeMaxDynamicSharedMemorySize, SMEMB);
    prep_b<<<64, 256>>>(wg, wn);
    gemm_mma_kernel<<<128, 512, SMEMB>>>(x);
    router_kernel<<<NTOK / 8, 256>>>(eps, out);
}

// round 5
// speedup vs baseline: 2.7297x; 1.0867x over previous
#include <cuda_runtime.h>
#include <cuda_fp16.h>
#include <cstdint>
#include <cmath>

// ---------------- problem constants ----------------
#define NTOK 8192      // B*T
#define DDIM 2048
#define NE   64

// output layout (concatenated float32)
#define P_OFF 0
#define I_OFF (NTOK * NE)
#define M_OFF (I_OFF + NTOK * 2)

// ---------------- GEMM tiling ----------------
#define KSPLIT 2
#define KQ     1024           // K per split
#define CHK    32             // k per chunk
#define NCH    32             // chunks (KQ/CHK)
#define AROW   80             // A smem row stride bytes (64B data + 16B pad)
#define BROW   272            // B smem row stride bytes (256B data + 16B pad)
#define A_PL   (128 * AROW)   // A plane: 128 tokens            (10240)
#define B_PL   (32 * BROW)    // B plane: 32 k rows x 128 cols  (8704)
#define A_SZ   (2 * A_PL)
#define B_SZ   (2 * B_PL)
#define BUF    (A_SZ + B_SZ)  // 37888
#define SMEMB  (2 * BUF)      // 75776, double buffered

// ---------------- scratch ----------------
__device__ float g_part[KSPLIT * NTOK * 128];   // k-split partials (8MB)
__device__ int   g_ctr[64];                     // per-tile arrival counters (self-resetting)

// ---------------- helpers ----------------
__device__ __forceinline__ uint32_t smem_u32(const void* p) {
    uint32_t a;
    asm("{ .reg .u64 t; cvta.to.shared.u64 t, %1; cvt.u32.u64 %0, t; }" : "=r"(a) : "l"(p));
    return a;
}
__device__ __forceinline__ void ldsm4(uint32_t (&r)[4], uint32_t addr) {
    asm volatile("ldmatrix.sync.aligned.m8n8.x4.shared.b16 {%0,%1,%2,%3}, [%4];"
                 : "=r"(r[0]), "=r"(r[1]), "=r"(r[2]), "=r"(r[3]) : "r"(addr));
}
__device__ __forceinline__ void ldsm4t(uint32_t (&r)[4], uint32_t addr) {
    asm volatile("ldmatrix.sync.aligned.m8n8.x4.trans.shared.b16 {%0,%1,%2,%3}, [%4];"
                 : "=r"(r[0]), "=r"(r[1]), "=r"(r[2]), "=r"(r[3]) : "r"(addr));
}
__device__ __forceinline__ void mma16816(float (&c)[4], const uint32_t (&a)[4],
                                         uint32_t b0, uint32_t b1) {
    asm volatile(
        "mma.sync.aligned.m16n8k16.row.col.f32.f16.f16.f32 "
        "{%0,%1,%2,%3},{%4,%5,%6,%7},{%8,%9},{%0,%1,%2,%3};"
        : "+f"(c[0]), "+f"(c[1]), "+f"(c[2]), "+f"(c[3])
        : "r"(a[0]), "r"(a[1]), "r"(a[2]), "r"(a[3]), "r"(b0), "r"(b1));
}
__device__ __forceinline__ uint32_t h2_bits(__half2 v) {
    return *reinterpret_cast<uint32_t*>(&v);
}
// split 8 fp32 -> 2 planes of 8 fp16 (packed uint4 each)
__device__ __forceinline__ void split8h(const float* f, uint4& H, uint4& L) {
    uint32_t hw[4], lw[4];
    #pragma unroll
    for (int i = 0; i < 4; i++) {
        float a = f[2 * i], b = f[2 * i + 1];
        __half2 hp = __floats2half2_rn(a, b);
        float ra = a - __low2float(hp);
        float rb = b - __high2float(hp);
        __half2 lp = __floats2half2_rn(ra, rb);
        hw[i] = h2_bits(hp); lw[i] = h2_bits(lp);
    }
    H = make_uint4(hw[0], hw[1], hw[2], hw[3]);
    L = make_uint4(lw[0], lw[1], lw[2], lw[3]);
}
__device__ __forceinline__ float softplus_f(float v) {
    return (v > 20.0f) ? v : log1pf(expf(v));
}
// merge two (top1, top2) candidate sets; order: larger value, ties -> smaller index
__device__ __forceinline__ void top2_merge(float& v1, int& i1, float& v2, int& i2,
                                           float ov1, int oi1, float ov2, int oi2) {
    bool ow = (ov1 > v1) || (ov1 == v1 && oi1 < i1);
    float nv1 = ow ? ov1 : v1;  int ni1 = ow ? oi1 : i1;
    float lv  = ow ? v1  : ov1; int li  = ow ? i1  : oi1;   // losing top
    float wv2 = ow ? ov2 : v2;  int wi2 = ow ? oi2 : i2;    // winner's second
    bool sw = (lv > wv2) || (lv == wv2 && li < wi2);
    v1 = nv1; i1 = ni1;
    v2 = sw ? lv : wv2; i2 = sw ? li : wi2;
}

// ---------------- fused GEMM + router ----------------
__global__ __launch_bounds__(512, 1) void gemm_fused(
    const float* __restrict__ x, const float* __restrict__ wg,
    const float* __restrict__ wn, const float* __restrict__ eps,
    float* __restrict__ out)
{
    extern __shared__ char smem[];
    __shared__ int s_flag;
    const uint32_t sb = smem_u32(smem);
    const int tid  = threadIdx.x;
    const int wid  = tid >> 5;
    const int lane = tid & 31;
    const int tile = blockIdx.x >> 1;
    const int ks   = blockIdx.x & 1;
    const long t0  = (long)tile * 128;
    const int kbase = ks * KQ;

    const int m0  = (wid & 3) * 32;    // warp m-group
    const int n0w = (wid >> 2) * 32;   // warp n-group

    const int am = tid >> 2;           // A fill: token row (0..127)
    const int aq = tid & 3;            // A fill: 16B slot (8 k)
    const int bh  = tid >> 8;          // B fill: 0=gate 1=noise
    const int bkk = (tid >> 3) & 31;   // B fill: k row in chunk
    const int bn0 = (tid & 7) * 8;     // B fill: first of 8 experts
    const float* wsel = bh ? wn : wg;

    float acc[2][4][4];
    #pragma unroll
    for (int a = 0; a < 2; a++)
        #pragma unroll
        for (int b = 0; b < 4; b++)
            #pragma unroll
            for (int c = 0; c < 4; c++) acc[a][b][c] = 0.0f;

    const int t4 = lane >> 3, r8 = lane & 7;
    const uint32_t a_lane = (uint32_t)(((t4 & 1) * 8 + r8) * AROW + (t4 >> 1) * 16);
    const uint32_t b_lane = (uint32_t)((lane & 15) * BROW + ((lane >> 4) * 8) * 2);

    // staged regs (chunk c+2 pipeline)
    float4 sxa, sxb, swa, swb;

    // ---- prologue: chunk 0 direct, stage chunk 1 ----
    {
        const float4* px = reinterpret_cast<const float4*>(x + (t0 + am) * DDIM + kbase + aq * 8);
        float4 xa = px[0], xb = px[1];
        const float4* pw = reinterpret_cast<const float4*>(wsel + (long)(kbase + bkk) * 64 + bn0);
        float4 wa = pw[0], wb = pw[1];
        float fx[8] = {xa.x, xa.y, xa.z, xa.w, xb.x, xb.y, xb.z, xb.w};
        uint4 H, L;
        split8h(fx, H, L);
        *reinterpret_cast<uint4*>(smem + 0 * A_PL + am * AROW + aq * 16) = H;
        *reinterpret_cast<uint4*>(smem + 1 * A_PL + am * AROW + aq * 16) = L;
        float fw[8] = {wa.x, wa.y, wa.z, wa.w, wb.x, wb.y, wb.z, wb.w};
        split8h(fw, H, L);
        *reinterpret_cast<uint4*>(smem + A_SZ + 0 * B_PL + bkk * BROW + (bh * 64 + bn0) * 2) = H;
        *reinterpret_cast<uint4*>(smem + A_SZ + 1 * B_PL + bkk * BROW + (bh * 64 + bn0) * 2) = L;
        const float4* px1 = reinterpret_cast<const float4*>(
            x + (t0 + am) * DDIM + kbase + CHK + aq * 8);
        sxa = px1[0]; sxb = px1[1];
        const float4* pw1 = reinterpret_cast<const float4*>(
            wsel + (long)(kbase + CHK + bkk) * 64 + bn0);
        swa = pw1[0]; swb = pw1[1];
    }

    #pragma unroll 1
    for (int c = 0; c < NCH; c++) {
        const uint32_t cur = (uint32_t)((c & 1) * BUF);
        const uint32_t nxt = (uint32_t)(((c + 1) & 1) * BUF);

        if (c + 1 < NCH) {   // store staged chunk c+1
            float fx[8] = {sxa.x, sxa.y, sxa.z, sxa.w, sxb.x, sxb.y, sxb.z, sxb.w};
            uint4 H, L;
            split8h(fx, H, L);
            *reinterpret_cast<uint4*>(smem + nxt + 0 * A_PL + am * AROW + aq * 16) = H;
            *reinterpret_cast<uint4*>(smem + nxt + 1 * A_PL + am * AROW + aq * 16) = L;
            float fw[8] = {swa.x, swa.y, swa.z, swa.w, swb.x, swb.y, swb.z, swb.w};
            split8h(fw, H, L);
            *reinterpret_cast<uint4*>(smem + nxt + A_SZ + 0 * B_PL + bkk * BROW + (bh * 64 + bn0) * 2) = H;
            *reinterpret_cast<uint4*>(smem + nxt + A_SZ + 1 * B_PL + bkk * BROW + (bh * 64 + bn0) * 2) = L;
        }
        if (c + 2 < NCH) {   // issue loads for chunk c+2
            const float4* px = reinterpret_cast<const float4*>(
                x + (t0 + am) * DDIM + kbase + (c + 2) * CHK + aq * 8);
            sxa = px[0]; sxb = px[1];
            const float4* pw = reinterpret_cast<const float4*>(
                wsel + (long)(kbase + (c + 2) * CHK + bkk) * 64 + bn0);
            swa = pw[0]; swb = pw[1];
        }
        __syncthreads();   // chunk c buffer visible

        const uint32_t aB = sb + cur;
        const uint32_t bB = sb + cur + A_SZ;
        #pragma unroll
        for (int s = 0; s < 2; s++) {
            uint32_t Ah[2][4], Al[2][4], Bh[2][4], Bl[2][4];
            #pragma unroll
            for (int mf = 0; mf < 2; mf++) {
                uint32_t base = aB + (uint32_t)((m0 + mf * 16) * AROW) + a_lane + s * 32;
                ldsm4(Ah[mf], base);
                ldsm4(Al[mf], base + A_PL);
            }
            #pragma unroll
            for (int q = 0; q < 2; q++) {
                uint32_t base = bB + (uint32_t)(s * 16 * BROW) + b_lane
                              + (uint32_t)((n0w + q * 16) * 2);
                ldsm4t(Bh[q], base);
                ldsm4t(Bl[q], base + B_PL);
            }
            #pragma unroll
            for (int mf = 0; mf < 2; mf++)
                #pragma unroll
                for (int nf = 0; nf < 4; nf++) {
                    int q = nf >> 1, oct = nf & 1;
                    uint32_t bh0 = Bh[q][oct * 2], bh1 = Bh[q][oct * 2 + 1];
                    uint32_t bl0 = Bl[q][oct * 2], bl1 = Bl[q][oct * 2 + 1];
                    mma16816(acc[mf][nf], Ah[mf], bh0, bh1);
                    mma16816(acc[mf][nf], Ah[mf], bl0, bl1);
                    mma16816(acc[mf][nf], Al[mf], bh0, bh1);
                }
        }
        __syncthreads();   // all reads of buffer c done before it is overwritten
    }

    // ---- epilogue: write k-split partials ----
    float* gp = g_part + (long)ks * NTOK * 128;
    #pragma unroll
    for (int mf = 0; mf < 2; mf++) {
        int tok = (int)t0 + m0 + mf * 16 + (lane >> 2);
        #pragma unroll
        for (int nf = 0; nf < 4; nf++) {
            int col = n0w + nf * 8 + (lane & 3) * 2;
            *reinterpret_cast<float2*>(&gp[(long)tok * 128 + col]) =
                make_float2(acc[mf][nf][0], acc[mf][nf][1]);
            *reinterpret_cast<float2*>(&gp[(long)(tok + 8) * 128 + col]) =
                make_float2(acc[mf][nf][2], acc[mf][nf][3]);
        }
    }

    // ---- arrival: second CTA of this tile runs the router ----
    __threadfence();
    if (tid == 0) {
        int old = atomicAdd(&g_ctr[tile], 1);
        s_flag = (old == 1);
        if (old == 1) g_ctr[tile] = 0;   // self-reset for graph replay
    }
    __syncthreads();
    if (!s_flag) return;
    __threadfence();   // acquire: see peer CTA's partials

    #pragma unroll 1
    for (int i = 0; i < 8; i++) {
        long t = t0 + wid * 8 + i;
        const float* P0 = g_part + t * 128;
        const float* P1 = g_part + (NTOK + t) * 128;
        float g0 = P0[lane]       + P1[lane];
        float g1 = P0[lane + 32]  + P1[lane + 32];
        float n0 = P0[64 + lane]  + P1[64 + lane];
        float n1 = P0[96 + lane]  + P1[96 + lane];
        float l0 = g0 + softplus_f(n0) * eps[t * NE + lane];
        float l1 = g1 + softplus_f(n1) * eps[t * NE + lane + 32];

        float v1, v2; int i1, i2;
        if (l0 >= l1) { v1 = l0; i1 = lane;      v2 = l1; i2 = lane + 32; }
        else          { v1 = l1; i1 = lane + 32; v2 = l0; i2 = lane; }
        #pragma unroll
        for (int off = 16; off; off >>= 1) {
            float ov1 = __shfl_xor_sync(0xffffffffu, v1, off);
            int   oi1 = __shfl_xor_sync(0xffffffffu, i1, off);
            float ov2 = __shfl_xor_sync(0xffffffffu, v2, off);
            int   oi2 = __shfl_xor_sync(0xffffffffu, i2, off);
            top2_merge(v1, i1, v2, i2, ov1, oi1, ov2, oi2);
        }

        float e  = expf(v2 - v1);
        float p1 = 1.0f / (1.0f + e);
        float p2 = e * p1;

        float pr0 = (lane == i1) ? p1 : ((lane == i2) ? p2 : 0.0f);
        float pr1 = ((lane + 32) == i1) ? p1 : (((lane + 32) == i2) ? p2 : 0.0f);
        out[P_OFF + t * NE + lane]      = pr0;
        out[P_OFF + t * NE + lane + 32] = pr1;
        if (lane == 0) {
            out[I_OFF + t * 2 + 0] = (float)i1;
            out[I_OFF + t * 2 + 1] = (float)i2;
        }
        out[M_OFF + t * NE + lane]      = (lane == i1) ? 1.0f : 0.0f;
        out[M_OFF + t * NE + lane + 32] = ((lane + 32) == i1) ? 1.0f : 0.0f;
        out[M_OFF + (long)NTOK * NE + t * NE + lane]      = (lane == i2) ? 1.0f : 0.0f;
        out[M_OFF + (long)NTOK * NE + t * NE + lane + 32] = ((lane + 32) == i2) ? 1.0f : 0.0f;
    }
}

extern "C" void kernel_launch(void* const* d_in, const int* in_sizes, int n_in,
                              void* d_out, int out_size)
{
    const float* x   = (const float*)d_in[0];  // [4,2048,2048]
    const float* eps = (const float*)d_in[1];  // [4,2048,64]
    const float* wg  = (const float*)d_in[2];  // [2048,64]
    const float* wn  = (const float*)d_in[3];  // [2048,64]
    float* out = (float*)d_out;

    cudaFuncSetAttribute(gemm_fused, cudaFuncAttributeMaxDynamicSharedMemorySize, SMEMB);
    gemm_fused<<<128, 512, SMEMB>>>(x, wg, wn, eps, out);
}